// round 1
// baseline (speedup 1.0000x reference)
#include <cuda_runtime.h>
#include <math.h>

#define NNODES 50000
#define NEDGES 800000
#define FEAT   120
#define NH     4

// Scratch (static __device__ arrays — allocation-free per harness rules)
__device__ float g_qW[(size_t)NNODES * FEAT * NH];  // [n][f][h], 96 MB
__device__ float g_k [(size_t)NNODES * FEAT];       // 24 MB
__device__ float g_v [(size_t)NNODES * FEAT];       // 24 MB
__device__ float g_z [NNODES];
__device__ float g_exp[NEDGES];

// ---------------------------------------------------------------------------
// Kernel 1: per-node. q/k/v = norm_act(o3_linear(x, W*)); qW = q contracted
// with Wd (normalizations folded); out initialized to v_node; z zeroed.
// One warp per node, 8 nodes per 256-thread block.
// ---------------------------------------------------------------------------
__global__ __launch_bounds__(256) void node_kernel(
    const float* __restrict__ x,
    const float* __restrict__ Wq0, const float* __restrict__ Wq1, const float* __restrict__ Wq2,
    const float* __restrict__ Wk0, const float* __restrict__ Wk1, const float* __restrict__ Wk2,
    const float* __restrict__ Wv0, const float* __restrict__ Wv1, const float* __restrict__ Wv2,
    const float* __restrict__ Wd0, const float* __restrict__ Wd1, const float* __restrict__ Wd2,
    float* __restrict__ out)
{
    __shared__ float sX[8][FEAT];
    __shared__ float sQ[8][FEAT];
    __shared__ float sT[8][FEAT];

    const int warp = threadIdx.x >> 5;
    const int lane = threadIdx.x & 31;
    const int n = blockIdx.x * 8 + warp;
    if (n >= NNODES) return;

    float* xs = sX[warp];
    float* qs = sQ[warp];
    float* ts = sT[warp];

    for (int f = lane; f < FEAT; f += 32) xs[f] = x[(size_t)n * FEAT + f];
    if (lane == 0) g_z[n] = 0.0f;
    __syncwarp();

    const float inv_s32 = 1.0f / sqrtf(32.0f);
    const float inv_s16 = 0.25f;
    const float inv_s8  = 1.0f / sqrtf(8.0f);

    #pragma unroll 1
    for (int pass = 0; pass < 3; ++pass) {
        const float* W0 = (pass == 0) ? Wq0 : ((pass == 1) ? Wk0 : Wv0);
        const float* W1 = (pass == 0) ? Wq1 : ((pass == 1) ? Wk1 : Wv1);
        const float* W2 = (pass == 0) ? Wq2 : ((pass == 1) ? Wk2 : Wv2);
        float* dstS = (pass == 0) ? qs : ts;

        // l=0: 32 rows (scalar irreps), one per lane
        {
            float acc = 0.0f;
            #pragma unroll
            for (int i = 0; i < 32; ++i) acc += xs[i] * __ldg(&W0[i * 32 + lane]);
            acc *= inv_s32;
            float nn = sqrtf(acc * acc + 1e-10f);
            float sc = (1.0f / (1.0f + expf(-nn))) / nn;
            dstS[lane] = sc * acc;
        }
        // l=1: 16 rows x 3 comps, lanes 0..15
        if (lane < 16) {
            float r[3];
            float ss = 0.0f;
            #pragma unroll
            for (int m = 0; m < 3; ++m) {
                float acc = 0.0f;
                #pragma unroll
                for (int i = 0; i < 16; ++i) acc += xs[32 + i * 3 + m] * __ldg(&W1[i * 16 + lane]);
                acc *= inv_s16;
                r[m] = acc; ss += acc * acc;
            }
            float nn = sqrtf(ss + 1e-10f);
            float sc = (1.0f / (1.0f + expf(-nn))) / nn;
            #pragma unroll
            for (int m = 0; m < 3; ++m) dstS[32 + lane * 3 + m] = sc * r[m];
        }
        // l=2: 8 rows x 5 comps, lanes 16..23
        else if (lane < 24) {
            const int o = lane - 16;
            float r[5];
            float ss = 0.0f;
            #pragma unroll
            for (int m = 0; m < 5; ++m) {
                float acc = 0.0f;
                #pragma unroll
                for (int i = 0; i < 8; ++i) acc += xs[80 + i * 5 + m] * __ldg(&W2[i * 8 + o]);
                acc *= inv_s8;
                r[m] = acc; ss += acc * acc;
            }
            float nn = sqrtf(ss + 1e-10f);
            float sc = (1.0f / (1.0f + expf(-nn))) / nn;
            #pragma unroll
            for (int m = 0; m < 5; ++m) dstS[80 + o * 5 + m] = sc * r[m];
        }
        __syncwarp();

        if (pass == 1) {
            float* kp = g_k + (size_t)n * FEAT;
            for (int f = lane; f < FEAT; f += 32) kp[f] = ts[f];
        } else if (pass == 2) {
            float* vp = g_v + (size_t)n * FEAT;
            float* op = out + (size_t)n * FEAT;
            for (int f = lane; f < FEAT; f += 32) { float v = ts[f]; vp[f] = v; op[f] = v; }
        }
        __syncwarp();
    }

    // qW[n][f][4]: contract q with Wd (tp_dot normalization folded)
    const float c0 = 1.0f / sqrtf(2112.0f);           // l=0
    const float c1 = c0 / sqrtf(3.0f);                 // l=1
    const float c2 = c0 / sqrtf(5.0f);                 // l=2
    float4* qw = reinterpret_cast<float4*>(g_qW) + (size_t)n * FEAT;
    const float4* D0 = reinterpret_cast<const float4*>(Wd0);
    const float4* D1 = reinterpret_cast<const float4*>(Wd1);
    const float4* D2 = reinterpret_cast<const float4*>(Wd2);

    // l=0: j = lane (32 outputs)
    {
        float4 a = make_float4(0.f, 0.f, 0.f, 0.f);
        #pragma unroll
        for (int i = 0; i < 32; ++i) {
            float qi = qs[i];
            float4 w = __ldg(&D0[i * 32 + lane]);
            a.x += qi * w.x; a.y += qi * w.y; a.z += qi * w.z; a.w += qi * w.w;
        }
        qw[lane] = make_float4(a.x * c0, a.y * c0, a.z * c0, a.w * c0);
    }
    // l=1: j = lane (lanes 0..15), m = 0..2
    if (lane < 16) {
        #pragma unroll
        for (int m = 0; m < 3; ++m) {
            float4 a = make_float4(0.f, 0.f, 0.f, 0.f);
            #pragma unroll
            for (int i = 0; i < 16; ++i) {
                float qi = qs[32 + i * 3 + m];
                float4 w = __ldg(&D1[i * 16 + lane]);
                a.x += qi * w.x; a.y += qi * w.y; a.z += qi * w.z; a.w += qi * w.w;
            }
            qw[32 + lane * 3 + m] = make_float4(a.x * c1, a.y * c1, a.z * c1, a.w * c1);
        }
    }
    // l=2: j = lane-16 (lanes 16..23), m = 0..4
    else if (lane < 24) {
        const int j = lane - 16;
        #pragma unroll
        for (int m = 0; m < 5; ++m) {
            float4 a = make_float4(0.f, 0.f, 0.f, 0.f);
            #pragma unroll
            for (int i = 0; i < 8; ++i) {
                float qi = qs[80 + i * 5 + m];
                float4 w = __ldg(&D2[i * 8 + j]);
                a.x += qi * w.x; a.y += qi * w.y; a.z += qi * w.z; a.w += qi * w.w;
            }
            qw[80 + j * 5 + m] = make_float4(a.x * c2, a.y * c2, a.z * c2, a.w * c2);
        }
    }
}

// ---------------------------------------------------------------------------
// Kernel 2: per-edge attention score. One warp per edge.
// s[h] = dot(qW[dst,:,h], k[src,:]); e = mean_h exp(s[h]); z[dst] += e.
// ---------------------------------------------------------------------------
__global__ __launch_bounds__(256) void edge_score_kernel(
    const int* __restrict__ dsts, const int* __restrict__ srcs)
{
    const int e = (blockIdx.x * blockDim.x + threadIdx.x) >> 5;
    const int lane = threadIdx.x & 31;
    if (e >= NEDGES) return;
    const int d = dsts[e];
    const int s = srcs[e];

    const float4* qw = reinterpret_cast<const float4*>(g_qW) + (size_t)d * FEAT;
    const float*  kk = g_k + (size_t)s * FEAT;

    float ax = 0.f, ay = 0.f, az = 0.f, aw = 0.f;
    #pragma unroll
    for (int it = 0; it < 4; ++it) {
        int f = lane + it * 32;
        if (f < FEAT) {
            float kf = kk[f];
            float4 w = qw[f];
            ax += w.x * kf; ay += w.y * kf; az += w.z * kf; aw += w.w * kf;
        }
    }
    #pragma unroll
    for (int off = 16; off > 0; off >>= 1) {
        ax += __shfl_xor_sync(0xffffffffu, ax, off);
        ay += __shfl_xor_sync(0xffffffffu, ay, off);
        az += __shfl_xor_sync(0xffffffffu, az, off);
        aw += __shfl_xor_sync(0xffffffffu, aw, off);
    }
    if (lane == 0) {
        float ev = 0.25f * (expf(ax) + expf(ay) + expf(az) + expf(aw));
        g_exp[e] = ev;
        atomicAdd(&g_z[d], ev);
    }
}

// ---------------------------------------------------------------------------
// Kernel 3: per-edge aggregation. out[dst] += sqrt(exp_e / z[dst]) * v[src].
// One warp per edge.
// ---------------------------------------------------------------------------
__global__ __launch_bounds__(256) void edge_agg_kernel(
    const int* __restrict__ dsts, const int* __restrict__ srcs,
    float* __restrict__ out)
{
    const int e = (blockIdx.x * blockDim.x + threadIdx.x) >> 5;
    const int lane = threadIdx.x & 31;
    if (e >= NEDGES) return;
    const int d = dsts[e];
    const int s = srcs[e];

    const float w = sqrtf(g_exp[e] / g_z[d]);
    const float* vv = g_v + (size_t)s * FEAT;
    float* oo = out + (size_t)d * FEAT;
    #pragma unroll
    for (int it = 0; it < 4; ++it) {
        int f = lane + it * 32;
        if (f < FEAT) atomicAdd(&oo[f], w * vv[f]);
    }
}

// ---------------------------------------------------------------------------
extern "C" void kernel_launch(void* const* d_in, const int* in_sizes, int n_in,
                              void* d_out, int out_size)
{
    const float* x   = (const float*)d_in[0];
    const float* Wq0 = (const float*)d_in[1];
    const float* Wq1 = (const float*)d_in[2];
    const float* Wq2 = (const float*)d_in[3];
    const float* Wk0 = (const float*)d_in[4];
    const float* Wk1 = (const float*)d_in[5];
    const float* Wk2 = (const float*)d_in[6];
    const float* Wv0 = (const float*)d_in[7];
    const float* Wv1 = (const float*)d_in[8];
    const float* Wv2 = (const float*)d_in[9];
    const float* Wd0 = (const float*)d_in[10];
    const float* Wd1 = (const float*)d_in[11];
    const float* Wd2 = (const float*)d_in[12];
    const int* edge_dst = (const int*)d_in[13];
    const int* edge_src = (const int*)d_in[14];
    float* out = (float*)d_out;

    // Kernel 1: 8 nodes per block (one warp each)
    int nblocks1 = (NNODES + 7) / 8;
    node_kernel<<<nblocks1, 256>>>(x, Wq0, Wq1, Wq2, Wk0, Wk1, Wk2,
                                   Wv0, Wv1, Wv2, Wd0, Wd1, Wd2, out);

    // Kernels 2/3: 8 edges per block (one warp each)
    int nblocks2 = (NEDGES + 7) / 8;
    edge_score_kernel<<<nblocks2, 256>>>(edge_dst, edge_src);
    edge_agg_kernel<<<nblocks2, 256>>>(edge_dst, edge_src, out);
}

// round 2
// speedup vs baseline: 1.0491x; 1.0491x over previous
#include <cuda_runtime.h>
#include <cuda_fp16.h>
#include <math.h>

#define NNODES 50000
#define NEDGES 800000
#define FEAT   120
#define NH     4

// Scratch (static __device__ arrays — allocation-free per harness rules)
__device__ __half2 g_qWh[(size_t)NNODES * FEAT * 2]; // [n][f][2x half2] = 4 heads, 48 MB
__device__ __half  g_kh [(size_t)NNODES * FEAT];     // 12 MB
__device__ float   g_v  [(size_t)NNODES * FEAT];     // 24 MB
__device__ float   g_z  [NNODES];
__device__ float   g_exp[NEDGES];

// ---------------------------------------------------------------------------
// Kernel 1: per-node. q/k/v = norm_act(o3_linear(x, W*)); qW = q contracted
// with Wd (normalizations folded, stored fp16); out initialized to v_node.
// One warp per node, 8 nodes per 256-thread block.
// ---------------------------------------------------------------------------
__global__ __launch_bounds__(256) void node_kernel(
    const float* __restrict__ x,
    const float* __restrict__ Wq0, const float* __restrict__ Wq1, const float* __restrict__ Wq2,
    const float* __restrict__ Wk0, const float* __restrict__ Wk1, const float* __restrict__ Wk2,
    const float* __restrict__ Wv0, const float* __restrict__ Wv1, const float* __restrict__ Wv2,
    const float* __restrict__ Wd0, const float* __restrict__ Wd1, const float* __restrict__ Wd2,
    float* __restrict__ out)
{
    __shared__ float sX[8][FEAT];
    __shared__ float sQ[8][FEAT];
    __shared__ float sT[8][FEAT];

    const int warp = threadIdx.x >> 5;
    const int lane = threadIdx.x & 31;
    const int n = blockIdx.x * 8 + warp;
    if (n >= NNODES) return;

    float* xs = sX[warp];
    float* qs = sQ[warp];
    float* ts = sT[warp];

    for (int f = lane; f < FEAT; f += 32) xs[f] = x[(size_t)n * FEAT + f];
    if (lane == 0) g_z[n] = 0.0f;
    __syncwarp();

    const float inv_s32 = 1.0f / sqrtf(32.0f);
    const float inv_s16 = 0.25f;
    const float inv_s8  = 1.0f / sqrtf(8.0f);

    #pragma unroll 1
    for (int pass = 0; pass < 3; ++pass) {
        const float* W0 = (pass == 0) ? Wq0 : ((pass == 1) ? Wk0 : Wv0);
        const float* W1 = (pass == 0) ? Wq1 : ((pass == 1) ? Wk1 : Wv1);
        const float* W2 = (pass == 0) ? Wq2 : ((pass == 1) ? Wk2 : Wv2);
        float* dstS = (pass == 0) ? qs : ts;

        // l=0: 32 rows (scalar irreps), one per lane
        {
            float acc = 0.0f;
            #pragma unroll
            for (int i = 0; i < 32; ++i) acc += xs[i] * __ldg(&W0[i * 32 + lane]);
            acc *= inv_s32;
            float nn = sqrtf(acc * acc + 1e-10f);
            float sc = (1.0f / (1.0f + expf(-nn))) / nn;
            dstS[lane] = sc * acc;
        }
        // l=1: 16 rows x 3 comps, lanes 0..15
        if (lane < 16) {
            float r[3];
            float ss = 0.0f;
            #pragma unroll
            for (int m = 0; m < 3; ++m) {
                float acc = 0.0f;
                #pragma unroll
                for (int i = 0; i < 16; ++i) acc += xs[32 + i * 3 + m] * __ldg(&W1[i * 16 + lane]);
                acc *= inv_s16;
                r[m] = acc; ss += acc * acc;
            }
            float nn = sqrtf(ss + 1e-10f);
            float sc = (1.0f / (1.0f + expf(-nn))) / nn;
            #pragma unroll
            for (int m = 0; m < 3; ++m) dstS[32 + lane * 3 + m] = sc * r[m];
        }
        // l=2: 8 rows x 5 comps, lanes 16..23
        else if (lane < 24) {
            const int o = lane - 16;
            float r[5];
            float ss = 0.0f;
            #pragma unroll
            for (int m = 0; m < 5; ++m) {
                float acc = 0.0f;
                #pragma unroll
                for (int i = 0; i < 8; ++i) acc += xs[80 + i * 5 + m] * __ldg(&W2[i * 8 + o]);
                acc *= inv_s8;
                r[m] = acc; ss += acc * acc;
            }
            float nn = sqrtf(ss + 1e-10f);
            float sc = (1.0f / (1.0f + expf(-nn))) / nn;
            #pragma unroll
            for (int m = 0; m < 5; ++m) dstS[80 + o * 5 + m] = sc * r[m];
        }
        __syncwarp();

        if (pass == 1) {
            __half* kp = g_kh + (size_t)n * FEAT;
            for (int f = lane; f < FEAT; f += 32) kp[f] = __float2half_rn(ts[f]);
        } else if (pass == 2) {
            float* vp = g_v + (size_t)n * FEAT;
            float* op = out + (size_t)n * FEAT;
            for (int f = lane; f < FEAT; f += 32) { float v = ts[f]; vp[f] = v; op[f] = v; }
        }
        __syncwarp();
    }

    // qW[n][f][4 heads]: contract q with Wd (tp_dot normalization folded), fp16 store
    const float c0 = 1.0f / sqrtf(2112.0f);            // l=0
    const float c1 = c0 / sqrtf(3.0f);                 // l=1
    const float c2 = c0 / sqrtf(5.0f);                 // l=2
    __half2* qw = g_qWh + (size_t)n * FEAT * 2;
    const float4* D0 = reinterpret_cast<const float4*>(Wd0);
    const float4* D1 = reinterpret_cast<const float4*>(Wd1);
    const float4* D2 = reinterpret_cast<const float4*>(Wd2);

    // l=0: j = lane (32 outputs)
    {
        float4 a = make_float4(0.f, 0.f, 0.f, 0.f);
        #pragma unroll
        for (int i = 0; i < 32; ++i) {
            float qi = qs[i];
            float4 w = __ldg(&D0[i * 32 + lane]);
            a.x += qi * w.x; a.y += qi * w.y; a.z += qi * w.z; a.w += qi * w.w;
        }
        qw[2 * lane + 0] = __floats2half2_rn(a.x * c0, a.y * c0);
        qw[2 * lane + 1] = __floats2half2_rn(a.z * c0, a.w * c0);
    }
    // l=1: j = lane (lanes 0..15), m = 0..2
    if (lane < 16) {
        #pragma unroll
        for (int m = 0; m < 3; ++m) {
            float4 a = make_float4(0.f, 0.f, 0.f, 0.f);
            #pragma unroll
            for (int i = 0; i < 16; ++i) {
                float qi = qs[32 + i * 3 + m];
                float4 w = __ldg(&D1[i * 16 + lane]);
                a.x += qi * w.x; a.y += qi * w.y; a.z += qi * w.z; a.w += qi * w.w;
            }
            int f = 32 + lane * 3 + m;
            qw[2 * f + 0] = __floats2half2_rn(a.x * c1, a.y * c1);
            qw[2 * f + 1] = __floats2half2_rn(a.z * c1, a.w * c1);
        }
    }
    // l=2: j = lane-16 (lanes 16..23), m = 0..4
    else if (lane < 24) {
        const int j = lane - 16;
        #pragma unroll
        for (int m = 0; m < 5; ++m) {
            float4 a = make_float4(0.f, 0.f, 0.f, 0.f);
            #pragma unroll
            for (int i = 0; i < 8; ++i) {
                float qi = qs[80 + i * 5 + m];
                float4 w = __ldg(&D2[i * 8 + j]);
                a.x += qi * w.x; a.y += qi * w.y; a.z += qi * w.z; a.w += qi * w.w;
            }
            int f = 80 + j * 5 + m;
            qw[2 * f + 0] = __floats2half2_rn(a.x * c2, a.y * c2);
            qw[2 * f + 1] = __floats2half2_rn(a.z * c2, a.w * c2);
        }
    }
}

// ---------------------------------------------------------------------------
// Kernel 2: per-edge attention score. One warp per edge (fp16 operands).
// s[h] = dot(qW[dst,:,h], k[src,:]); e = mean_h exp(s[h]); z[dst] += e.
// ---------------------------------------------------------------------------
__global__ __launch_bounds__(256) void edge_score_kernel(
    const int* __restrict__ dsts, const int* __restrict__ srcs)
{
    const int e = (blockIdx.x * blockDim.x + threadIdx.x) >> 5;
    const int lane = threadIdx.x & 31;
    if (e >= NEDGES) return;
    const int d = dsts[e];
    const int s = srcs[e];

    const uint2*  qw = reinterpret_cast<const uint2*>(g_qWh + (size_t)d * FEAT * 2);
    const __half* kk = g_kh + (size_t)s * FEAT;

    float ax = 0.f, ay = 0.f, az = 0.f, aw = 0.f;
    #pragma unroll
    for (int it = 0; it < 4; ++it) {
        int f = lane + it * 32;
        if (f < FEAT) {
            float kf = __half2float(kk[f]);
            uint2 wv = qw[f];
            float2 p01 = __half22float2(*reinterpret_cast<__half2*>(&wv.x));
            float2 p23 = __half22float2(*reinterpret_cast<__half2*>(&wv.y));
            ax += p01.x * kf; ay += p01.y * kf; az += p23.x * kf; aw += p23.y * kf;
        }
    }
    #pragma unroll
    for (int off = 16; off > 0; off >>= 1) {
        ax += __shfl_xor_sync(0xffffffffu, ax, off);
        ay += __shfl_xor_sync(0xffffffffu, ay, off);
        az += __shfl_xor_sync(0xffffffffu, az, off);
        aw += __shfl_xor_sync(0xffffffffu, aw, off);
    }
    if (lane == 0) {
        float ev = 0.25f * (expf(ax) + expf(ay) + expf(az) + expf(aw));
        g_exp[e] = ev;
        atomicAdd(&g_z[d], ev);
    }
}

// ---------------------------------------------------------------------------
// Kernel 3: per-edge aggregation. out[dst] += sqrt(exp_e / z[dst]) * v[src].
// One warp per edge; 30 active lanes, each handling a float4 via red.v4.
// ---------------------------------------------------------------------------
__global__ __launch_bounds__(256) void edge_agg_kernel(
    const int* __restrict__ dsts, const int* __restrict__ srcs,
    float* __restrict__ out)
{
    const int e = (blockIdx.x * blockDim.x + threadIdx.x) >> 5;
    const int lane = threadIdx.x & 31;
    if (e >= NEDGES) return;
    const int d = dsts[e];
    const int s = srcs[e];

    const float w = sqrtf(g_exp[e] / g_z[d]);

    if (lane < FEAT / 4) {  // 30 lanes
        const float4* vv = reinterpret_cast<const float4*>(g_v + (size_t)s * FEAT);
        float4 v4 = vv[lane];
        float* p = out + (size_t)d * FEAT + lane * 4;
        asm volatile("red.global.add.v4.f32 [%0], {%1, %2, %3, %4};"
                     :: "l"(p), "f"(w * v4.x), "f"(w * v4.y), "f"(w * v4.z), "f"(w * v4.w)
                     : "memory");
    }
}

// ---------------------------------------------------------------------------
extern "C" void kernel_launch(void* const* d_in, const int* in_sizes, int n_in,
                              void* d_out, int out_size)
{
    const float* x   = (const float*)d_in[0];
    const float* Wq0 = (const float*)d_in[1];
    const float* Wq1 = (const float*)d_in[2];
    const float* Wq2 = (const float*)d_in[3];
    const float* Wk0 = (const float*)d_in[4];
    const float* Wk1 = (const float*)d_in[5];
    const float* Wk2 = (const float*)d_in[6];
    const float* Wv0 = (const float*)d_in[7];
    const float* Wv1 = (const float*)d_in[8];
    const float* Wv2 = (const float*)d_in[9];
    const float* Wd0 = (const float*)d_in[10];
    const float* Wd1 = (const float*)d_in[11];
    const float* Wd2 = (const float*)d_in[12];
    const int* edge_dst = (const int*)d_in[13];
    const int* edge_src = (const int*)d_in[14];
    float* out = (float*)d_out;

    // Kernel 1: 8 nodes per block (one warp each)
    int nblocks1 = (NNODES + 7) / 8;
    node_kernel<<<nblocks1, 256>>>(x, Wq0, Wq1, Wq2, Wk0, Wk1, Wk2,
                                   Wv0, Wv1, Wv2, Wd0, Wd1, Wd2, out);

    // Kernels 2/3: 8 edges per block (one warp each)
    int nblocks2 = (NEDGES + 7) / 8;
    edge_score_kernel<<<nblocks2, 256>>>(edge_dst, edge_src);
    edge_agg_kernel<<<nblocks2, 256>>>(edge_dst, edge_src, out);
}